// round 5
// baseline (speedup 1.0000x reference)
#include <cuda_runtime.h>
#include <math.h>

#define MAXN 50048
#define MAXE 640000
#define D 128

// ---------------- scratch (device globals; no runtime allocation) ----------------
__device__ float g_h_env[MAXN * D];
__device__ float g_sdst_env[MAXN];
__device__ float g_ssrc_env[MAXN];
__device__ float2 g_h_in[MAXN];
__device__ float2 g_h_out[MAXN];
__device__ float g_sdst_in[MAXN], g_ssrc_in[MAXN], g_sdst_out[MAXN], g_ssrc_out[MAXN];
__device__ float2 g_inlog[MAXN], g_outlog[MAXN];
__device__ int g_m_in[MAXN], g_m_out[MAXN], g_m_env[MAXN];
__device__ float g_den_in[MAXN], g_den_out[MAXN], g_den_env[MAXN];
__device__ float2 g_elog_io[MAXE];
__device__ float2 g_e_io[MAXE];
__device__ float g_elog_env[MAXE];
__device__ float g_e_env[MAXE];
__device__ unsigned char g_keep_in[MAXN], g_keep_out[MAXN];
__device__ float g_srel[6];   // [0,1]=in t0,t1  [2,3]=out  [4,5]=env

// ---------------- helpers ----------------
__device__ __forceinline__ int ford(float f) {
    int i = __float_as_int(f);
    return i >= 0 ? i : i ^ 0x7FFFFFFF;
}
__device__ __forceinline__ float funord(int i) {
    return __int_as_float(i >= 0 ? i : i ^ 0x7FFFFFFF);
}
__device__ __forceinline__ float lrelu(float v) { return v >= 0.f ? v : 0.2f * v; }

__device__ __forceinline__ void red_add_v2(float2* p, float a, float b) {
    asm volatile("red.global.add.v2.f32 [%0], {%1, %2};"
                 :: "l"(p), "f"(a), "f"(b) : "memory");
}
__device__ __forceinline__ void red_add_v4(float* p, float a, float b, float c, float d) {
    asm volatile("red.global.add.v4.f32 [%0], {%1, %2, %3, %4};"
                 :: "l"(p), "f"(a), "f"(b), "f"(c), "f"(d) : "memory");
}

// ---------------- kernels ----------------
__global__ void k_init(int n) {
    int i = blockIdx.x * blockDim.x + threadIdx.x;
    if (i < n) {
        g_m_in[i] = g_m_out[i] = g_m_env[i] = (int)0x80000000;
        g_den_in[i] = g_den_out[i] = g_den_env[i] = 0.f;
    }
}

// compute s_rel for all 3 nets (tiny, 1 block)
__global__ void k_rel(const float* __restrict__ inWr, const float* __restrict__ inWrb,
                      const float* __restrict__ inAw, const float* __restrict__ inRel,
                      const float* __restrict__ outWr, const float* __restrict__ outWrb,
                      const float* __restrict__ outAw, const float* __restrict__ outRel,
                      const float* __restrict__ envWr, const float* __restrict__ envWrb,
                      const float* __restrict__ envAw, const float* __restrict__ envRel) {
    __shared__ float red[128];
    int t = threadIdx.x;  // 128 threads
    for (int tt = 0; tt < 2; tt++) {
        float r = envWrb[t];
        for (int k = 0; k < 100; k++) r += envRel[tt * 100 + k] * envWr[t * 100 + k];
        red[t] = r * envAw[256 + t];
        __syncthreads();
        for (int s = 64; s > 0; s >>= 1) {
            if (t < s) red[t] += red[t + s];
            __syncthreads();
        }
        if (t == 0) g_srel[4 + tt] = red[0];
        __syncthreads();
    }
    if (t == 0) {
        for (int tt = 0; tt < 2; tt++) {
            float s = 0.f;
            for (int j = 0; j < 2; j++) {
                float r = inWrb[j];
                for (int k = 0; k < 100; k++) r += inRel[tt * 100 + k] * inWr[j * 100 + k];
                s += r * inAw[4 + j];
            }
            g_srel[tt] = s;
        }
    } else if (t == 1) {
        for (int tt = 0; tt < 2; tt++) {
            float s = 0.f;
            for (int j = 0; j < 2; j++) {
                float r = outWrb[j];
                for (int k = 0; k < 100; k++) r += outRel[tt * 100 + k] * outWr[j * 100 + k];
                s += r * outAw[4 + j];
            }
            g_srel[2 + tt] = s;
        }
    }
}

// y = x @ W^T + b.  blockIdx.y==0 -> env_W into g_h_env ; ==1 -> env_Wres into d_out
#define BM 128
#define BN 128
#define BK 16
__global__ __launch_bounds__(256) void k_gemm(const float* __restrict__ x,
                                              const float* __restrict__ W0,
                                              const float* __restrict__ b0,
                                              const float* __restrict__ W1,
                                              const float* __restrict__ b1,
                                              float* __restrict__ out1, int n) {
    const float* W = blockIdx.y ? W1 : W0;
    const float* bias = blockIdx.y ? b1 : b0;
    float* out = blockIdx.y ? out1 : g_h_env;

    __shared__ float sx[BK][BM + 4];
    __shared__ float sw[BK][BN + 4];
    int row0 = blockIdx.x * BM;
    int tid = threadIdx.x;
    int ty = tid >> 4, tx = tid & 15;

    float acc[8][8];
#pragma unroll
    for (int i = 0; i < 8; i++)
#pragma unroll
        for (int j = 0; j < 8; j++) acc[i][j] = 0.f;

    for (int kk = 0; kk < 128; kk += BK) {
#pragma unroll
        for (int q = 0; q < 2; q++) {
            int f = tid * 2 + q;
            int r = f >> 2;
            int k4 = f & 3;
            float4 v = make_float4(0.f, 0.f, 0.f, 0.f);
            int gr = row0 + r;
            if (gr < n) v = *(const float4*)(x + gr * 128 + kk + k4 * 4);
            sx[k4 * 4 + 0][r] = v.x;
            sx[k4 * 4 + 1][r] = v.y;
            sx[k4 * 4 + 2][r] = v.z;
            sx[k4 * 4 + 3][r] = v.w;
        }
#pragma unroll
        for (int q = 0; q < 2; q++) {
            int f = tid * 2 + q;
            int c = f >> 2;
            int k4 = f & 3;
            float4 v = *(const float4*)(W + c * 128 + kk + k4 * 4);
            sw[k4 * 4 + 0][c] = v.x;
            sw[k4 * 4 + 1][c] = v.y;
            sw[k4 * 4 + 2][c] = v.z;
            sw[k4 * 4 + 3][c] = v.w;
        }
        __syncthreads();
#pragma unroll
        for (int k = 0; k < BK; k++) {
            float rm[8], rn[8];
#pragma unroll
            for (int i = 0; i < 8; i++) rm[i] = sx[k][ty * 8 + i];
#pragma unroll
            for (int j = 0; j < 8; j++) rn[j] = sw[k][tx * 8 + j];
#pragma unroll
            for (int i = 0; i < 8; i++)
#pragma unroll
                for (int j = 0; j < 8; j++) acc[i][j] += rm[i] * rn[j];
        }
        __syncthreads();
    }
#pragma unroll
    for (int i = 0; i < 8; i++) {
        int gr = row0 + ty * 8 + i;
        if (gr < n) {
#pragma unroll
            for (int j = 0; j < 8; j += 4) {
                int c = tx * 8 + j;
                float4 v = make_float4(acc[i][j] + bias[c], acc[i][j + 1] + bias[c + 1],
                                       acc[i][j + 2] + bias[c + 2], acc[i][j + 3] + bias[c + 3]);
                *(float4*)(out + gr * 128 + c) = v;
            }
        }
    }
}

// per-node: small nets (dout=2) + env attention scalars. One warp per node.
__global__ void k_node(const float* __restrict__ x,
                       const float* __restrict__ inW, const float* __restrict__ inWb,
                       const float* __restrict__ inAw,
                       const float* __restrict__ inWres, const float* __restrict__ inWresb,
                       const float* __restrict__ outW, const float* __restrict__ outWb,
                       const float* __restrict__ outAw,
                       const float* __restrict__ outWres, const float* __restrict__ outWresb,
                       const float* __restrict__ envAw, int n) {
    int warp = (blockIdx.x * blockDim.x + threadIdx.x) >> 5;
    int lane = threadIdx.x & 31;
    if (warp >= n) return;
    float4 xv = ((const float4*)x)[warp * 32 + lane];
    float4 hv = ((const float4*)g_h_env)[warp * 32 + lane];
    float f[10];
    {
        float4 w;
        w = ((const float4*)(inW))[lane];         f[0] = xv.x * w.x + xv.y * w.y + xv.z * w.z + xv.w * w.w;
        w = ((const float4*)(inW + 128))[lane];   f[1] = xv.x * w.x + xv.y * w.y + xv.z * w.z + xv.w * w.w;
        w = ((const float4*)(inWres))[lane];      f[2] = xv.x * w.x + xv.y * w.y + xv.z * w.z + xv.w * w.w;
        w = ((const float4*)(inWres + 128))[lane];f[3] = xv.x * w.x + xv.y * w.y + xv.z * w.z + xv.w * w.w;
        w = ((const float4*)(outW))[lane];        f[4] = xv.x * w.x + xv.y * w.y + xv.z * w.z + xv.w * w.w;
        w = ((const float4*)(outW + 128))[lane];  f[5] = xv.x * w.x + xv.y * w.y + xv.z * w.z + xv.w * w.w;
        w = ((const float4*)(outWres))[lane];     f[6] = xv.x * w.x + xv.y * w.y + xv.z * w.z + xv.w * w.w;
        w = ((const float4*)(outWres + 128))[lane];f[7] = xv.x * w.x + xv.y * w.y + xv.z * w.z + xv.w * w.w;
        w = ((const float4*)(envAw))[lane];       f[8] = hv.x * w.x + hv.y * w.y + hv.z * w.z + hv.w * w.w;
        w = ((const float4*)(envAw + 128))[lane]; f[9] = hv.x * w.x + hv.y * w.y + hv.z * w.z + hv.w * w.w;
    }
#pragma unroll
    for (int off = 16; off > 0; off >>= 1)
#pragma unroll
        for (int q = 0; q < 10; q++) f[q] += __shfl_xor_sync(0xffffffffu, f[q], off);
    if (lane == 0) {
        float2 hin = make_float2(f[0] + inWb[0], f[1] + inWb[1]);
        float2 hout = make_float2(f[4] + outWb[0], f[5] + outWb[1]);
        g_h_in[warp] = hin;
        g_h_out[warp] = hout;
        g_inlog[warp] = make_float2(f[2] + inWresb[0], f[3] + inWresb[1]);
        g_outlog[warp] = make_float2(f[6] + outWresb[0], f[7] + outWresb[1]);
        g_sdst_in[warp] = hin.x * inAw[0] + hin.y * inAw[1];
        g_ssrc_in[warp] = hin.x * inAw[2] + hin.y * inAw[3];
        g_sdst_out[warp] = hout.x * outAw[0] + hout.y * outAw[1];
        g_ssrc_out[warp] = hout.x * outAw[2] + hout.y * outAw[3];
        g_sdst_env[warp] = f[8];
        g_ssrc_env[warp] = f[9];
    }
}

__global__ void k_io1(const int* __restrict__ ei, const int* __restrict__ et,
                      const float* __restrict__ inAb, const float* __restrict__ outAb, int E) {
    int e = blockIdx.x * blockDim.x + threadIdx.x;
    if (e >= E) return;
    int s = ei[e], d = ei[E + e], t = et[e];
    float lin = lrelu(g_sdst_in[d] + g_ssrc_in[s] + g_srel[t] + inAb[0]);
    float lout = lrelu(g_sdst_out[d] + g_ssrc_out[s] + g_srel[2 + t] + outAb[0]);
    g_elog_io[e] = make_float2(lin, lout);
    atomicMax(&g_m_in[d], ford(lin));
    atomicMax(&g_m_out[d], ford(lout));
}

__global__ void k_io2(const int* __restrict__ ei, int E) {
    int e = blockIdx.x * blockDim.x + threadIdx.x;
    if (e >= E) return;
    int d = ei[E + e];
    float2 l = g_elog_io[e];
    float ein = expf(l.x - funord(g_m_in[d]));
    float eout = expf(l.y - funord(g_m_out[d]));
    g_e_io[e] = make_float2(ein, eout);
    atomicAdd(&g_den_in[d], ein);
    atomicAdd(&g_den_out[d], eout);
}

__global__ void k_io3(const int* __restrict__ ei, int E) {
    int e = blockIdx.x * blockDim.x + threadIdx.x;
    if (e >= E) return;
    int s = ei[e], d = ei[E + e];
    float2 ev = g_e_io[e];
    float ain = ev.x / fmaxf(g_den_in[d], 1e-16f);
    float aout = ev.y / fmaxf(g_den_out[d], 1e-16f);
    float2 hi = g_h_in[s], ho = g_h_out[s];
    red_add_v2(&g_inlog[d], ain * hi.x, ain * hi.y);
    red_add_v2(&g_outlog[d], aout * ho.x, aout * ho.y);
}

__global__ void k_decide(const float* __restrict__ gi, const float* __restrict__ go, int n) {
    int i = blockIdx.x * blockDim.x + threadIdx.x;
    if (i >= n) return;
    float2 il = g_inlog[i];
    float2 ol = g_outlog[i];
    g_keep_in[i] = (il.x + gi[2 * i]) >= (il.y + gi[2 * i + 1]) ? 1 : 0;
    g_keep_out[i] = (ol.x + go[2 * i]) >= (ol.y + go[2 * i + 1]) ? 1 : 0;
}

__global__ void k_env1(const int* __restrict__ ei, const int* __restrict__ et,
                       const float* __restrict__ envAb, int E) {
    int e = blockIdx.x * blockDim.x + threadIdx.x;
    if (e >= E) return;
    int s = ei[e], d = ei[E + e], t = et[e];
    float l;
    if (g_keep_in[d] && g_keep_out[s])
        l = lrelu(g_sdst_env[d] + g_ssrc_env[s] + g_srel[4 + t] + envAb[0]);
    else
        l = -1e9f;
    g_elog_env[e] = l;
    atomicMax(&g_m_env[d], ford(l));
}

__global__ void k_env2(const int* __restrict__ ei, int E) {
    int e = blockIdx.x * blockDim.x + threadIdx.x;
    if (e >= E) return;
    int s = ei[e], d = ei[E + e];
    float l = g_elog_env[e];
    float ev = 0.f;
    if (g_keep_in[d] && g_keep_out[s]) ev = expf(l - funord(g_m_env[d]));
    g_e_env[e] = ev;
    if (ev != 0.f) atomicAdd(&g_den_env[d], ev);
}

// heavy aggregation: one warp per edge, float4 vector reductions into d_out
__global__ void k_env3(const int* __restrict__ ei, float* __restrict__ out, int E) {
    int w = (blockIdx.x * blockDim.x + threadIdx.x) >> 5;
    int lane = threadIdx.x & 31;
    if (w >= E) return;
    float ev = g_e_env[w];
    if (ev == 0.f) return;
    int d = ei[E + w];
    float alpha = ev / fmaxf(g_den_env[d], 1e-16f);
    int s = ei[w];
    float4 hv = ((const float4*)g_h_env)[s * 32 + lane];
    red_add_v4(out + d * 128 + lane * 4, alpha * hv.x, alpha * hv.y, alpha * hv.z, alpha * hv.w);
}

// ---------------- launch ----------------
extern "C" void kernel_launch(void* const* d_in, const int* in_sizes, int n_in,
                              void* d_out, int out_size) {
    const float* x = (const float*)d_in[0];
    const int* ei = (const int*)d_in[1];
    const int* et = (const int*)d_in[2];
    const float* gi = (const float*)d_in[3];
    const float* go = (const float*)d_in[4];
    // inA
    const float* inW = (const float*)d_in[5];
    const float* inWb = (const float*)d_in[6];
    const float* inWr = (const float*)d_in[7];
    const float* inWrb = (const float*)d_in[8];
    const float* inAw = (const float*)d_in[9];
    const float* inAb = (const float*)d_in[10];
    const float* inWres = (const float*)d_in[11];
    const float* inWresb = (const float*)d_in[12];
    const float* inRel = (const float*)d_in[13];
    // outA
    const float* outW = (const float*)d_in[14];
    const float* outWb = (const float*)d_in[15];
    const float* outWr = (const float*)d_in[16];
    const float* outWrb = (const float*)d_in[17];
    const float* outAw = (const float*)d_in[18];
    const float* outAb = (const float*)d_in[19];
    const float* outWres = (const float*)d_in[20];
    const float* outWresb = (const float*)d_in[21];
    const float* outRel = (const float*)d_in[22];
    // env
    const float* envW = (const float*)d_in[23];
    const float* envWb = (const float*)d_in[24];
    const float* envWr = (const float*)d_in[25];
    const float* envWrb = (const float*)d_in[26];
    const float* envAw = (const float*)d_in[27];
    const float* envAb = (const float*)d_in[28];
    const float* envWres = (const float*)d_in[29];
    const float* envWresb = (const float*)d_in[30];
    const float* envRel = (const float*)d_in[31];

    float* out = (float*)d_out;
    int n = in_sizes[0] / 128;
    int E = in_sizes[2];

    k_init<<<(n + 255) / 256, 256>>>(n);
    k_rel<<<1, 128>>>(inWr, inWrb, inAw, inRel, outWr, outWrb, outAw, outRel,
                      envWr, envWrb, envAw, envRel);
    k_gemm<<<dim3((n + BM - 1) / BM, 2), 256>>>(x, envW, envWb, envWres, envWresb, out, n);
    k_node<<<(n * 32 + 255) / 256, 256>>>(x, inW, inWb, inAw, inWres, inWresb,
                                          outW, outWb, outAw, outWres, outWresb, envAw, n);
    k_io1<<<(E + 255) / 256, 256>>>(ei, et, inAb, outAb, E);
    k_io2<<<(E + 255) / 256, 256>>>(ei, E);
    k_io3<<<(E + 255) / 256, 256>>>(ei, E);
    k_decide<<<(n + 255) / 256, 256>>>(gi, go, n);
    k_env1<<<(E + 255) / 256, 256>>>(ei, et, envAb, E);
    k_env2<<<(E + 255) / 256, 256>>>(ei, E);
    k_env3<<<(E * 32 + 255) / 256, 256>>>(ei, out, E);
}

// round 6
// speedup vs baseline: 1.5871x; 1.5871x over previous
#include <cuda_runtime.h>
#include <math.h>

#define MAXN 50048
#define MAXE 640000

// ---------------- scratch (device globals) ----------------
__device__ float g_h_env[MAXN * 128];
__device__ float g_sdst_env[MAXN];
__device__ float g_ssrc_env[MAXN];
__device__ float2 g_sd_io[MAXN];    // (sdst_in, sdst_out)
__device__ float2 g_ss_io[MAXN];    // (ssrc_in, ssrc_out)
__device__ float4 g_hio[MAXN];      // (h_in.x, h_in.y, h_out.x, h_out.y)
__device__ float4 g_iolog[MAXN];    // (in0, in1, out0, out1) residual + aggr
__device__ int2   g_m_io[MAXN];
__device__ float2 g_den_io[MAXN];
__device__ float2 g_rden_io[MAXN];
__device__ float  g_den_env[MAXN];
__device__ float2 g_elog_io[MAXE];
__device__ float2 g_e_io[MAXE];
__device__ float  g_e_env[MAXE];
__device__ unsigned char g_keep[MAXN];
__device__ float g_srel[6];   // [0,1]=in(+bias)  [2,3]=out(+bias)  [4,5]=env(+bias)

// ---------------- helpers ----------------
__device__ __forceinline__ int ford(float f) {
    int i = __float_as_int(f);
    return i >= 0 ? i : i ^ 0x7FFFFFFF;
}
__device__ __forceinline__ float funord(int i) {
    return __int_as_float(i >= 0 ? i : i ^ 0x7FFFFFFF);
}
__device__ __forceinline__ float lrelu(float v) { return v >= 0.f ? v : 0.2f * v; }

__device__ __forceinline__ void red_add_v2(float2* p, float a, float b) {
    asm volatile("red.global.add.v2.f32 [%0], {%1, %2};"
                 :: "l"(p), "f"(a), "f"(b) : "memory");
}
__device__ __forceinline__ void red_add_v4(float* p, float a, float b, float c, float d) {
    asm volatile("red.global.add.v4.f32 [%0], {%1, %2, %3, %4};"
                 :: "l"(p), "f"(a), "f"(b), "f"(c), "f"(d) : "memory");
}
__device__ __forceinline__ unsigned int cvt_tf32(float v) {
    unsigned int r;
    asm("cvt.rna.tf32.f32 %0, %1;" : "=r"(r) : "f"(v));
    return r;
}
__device__ __forceinline__ uint4 cvt4(float4 v) {
    return make_uint4(cvt_tf32(v.x), cvt_tf32(v.y), cvt_tf32(v.z), cvt_tf32(v.w));
}
__device__ __forceinline__ void mma8(float* c, const unsigned int* a, const unsigned int* b) {
    asm volatile(
        "mma.sync.aligned.m16n8k8.row.col.f32.tf32.tf32.f32 "
        "{%0,%1,%2,%3}, {%4,%5,%6,%7}, {%8,%9}, {%0,%1,%2,%3};"
        : "+f"(c[0]), "+f"(c[1]), "+f"(c[2]), "+f"(c[3])
        : "r"(a[0]), "r"(a[1]), "r"(a[2]), "r"(a[3]), "r"(b[0]), "r"(b[1]));
}

// ---------------- init + s_rel (block 0 = rel, rest = init) ----------------
__global__ void k_initrel(const float* __restrict__ inWr, const float* __restrict__ inWrb,
                          const float* __restrict__ inAw, const float* __restrict__ inAb,
                          const float* __restrict__ inRel,
                          const float* __restrict__ outWr, const float* __restrict__ outWrb,
                          const float* __restrict__ outAw, const float* __restrict__ outAb,
                          const float* __restrict__ outRel,
                          const float* __restrict__ envWr, const float* __restrict__ envWrb,
                          const float* __restrict__ envAw, const float* __restrict__ envAb,
                          const float* __restrict__ envRel, int n) {
    int t = threadIdx.x;
    if (blockIdx.x == 0) {
        __shared__ float red[128];
        for (int tt = 0; tt < 2; tt++) {
            if (t < 128) {
                float r = envWrb[t];
                for (int k = 0; k < 100; k++) r += envRel[tt * 100 + k] * envWr[t * 100 + k];
                red[t] = r * envAw[256 + t];
            }
            __syncthreads();
            for (int s2 = 64; s2 > 0; s2 >>= 1) {
                if (t < s2) red[t] += red[t + s2];
                __syncthreads();
            }
            if (t == 0) g_srel[4 + tt] = red[0] + envAb[0];
            __syncthreads();
        }
        if (t == 0) {
            for (int tt = 0; tt < 2; tt++) {
                float s = 0.f;
                for (int j = 0; j < 2; j++) {
                    float r = inWrb[j];
                    for (int k = 0; k < 100; k++) r += inRel[tt * 100 + k] * inWr[j * 100 + k];
                    s += r * inAw[4 + j];
                }
                g_srel[tt] = s + inAb[0];
            }
        } else if (t == 32) {
            for (int tt = 0; tt < 2; tt++) {
                float s = 0.f;
                for (int j = 0; j < 2; j++) {
                    float r = outWrb[j];
                    for (int k = 0; k < 100; k++) r += outRel[tt * 100 + k] * outWr[j * 100 + k];
                    s += r * outAw[4 + j];
                }
                g_srel[2 + tt] = s + outAb[0];
            }
        }
    } else {
        int i = (blockIdx.x - 1) * 256 + t;
        if (i < n) {
            g_m_io[i] = make_int2((int)0x80000000, (int)0x80000000);
            g_den_io[i] = make_float2(0.f, 0.f);
            g_den_env[i] = 0.f;
            g_sdst_env[i] = 0.f;
            g_ssrc_env[i] = 0.f;
        }
    }
}

// ---------------- tf32 tensor-core GEMM: y = x @ W^T + b ----------------
// blockIdx.y==0 -> envW into g_h_env (+ env attention scalar epilogue)
// blockIdx.y==1 -> envWres into d_out (residual)
__global__ __launch_bounds__(256) void k_gemm(const float* __restrict__ x,
                                              const float* __restrict__ W0,
                                              const float* __restrict__ b0,
                                              const float* __restrict__ W1,
                                              const float* __restrict__ b1,
                                              const float* __restrict__ envAw,
                                              float* __restrict__ out1, int n) {
    const float* W = blockIdx.y ? W1 : W0;
    const float* bias = blockIdx.y ? b1 : b0;
    float* out = blockIdx.y ? out1 : g_h_env;
    const bool env = (blockIdx.y == 0);

    __shared__ uint4 sx4[128][9];   // 128 rows x 32 k, stride 36 floats (pad 4)
    __shared__ uint4 sw4[128][9];
    unsigned int (*sx)[36] = reinterpret_cast<unsigned int(*)[36]>(sx4);
    unsigned int (*sw)[36] = reinterpret_cast<unsigned int(*)[36]>(sw4);

    int tid = threadIdx.x;
    int lane = tid & 31;
    int wid = tid >> 5;
    int warp_m = wid >> 1;      // 0..3 -> 32-row tile
    int warp_n = wid & 1;       // 0..1 -> 64-col tile
    int g = lane >> 2, tig = lane & 3;
    int row0 = blockIdx.x * 128;

    float acc[2][8][4];
#pragma unroll
    for (int mt = 0; mt < 2; mt++)
#pragma unroll
        for (int nt = 0; nt < 8; nt++)
#pragma unroll
            for (int q = 0; q < 4; q++) acc[mt][nt][q] = 0.f;

    for (int kk = 0; kk < 128; kk += 32) {
        __syncthreads();
#pragma unroll
        for (int idx = tid; idx < 1024; idx += 256) {
            int r = idx >> 3, q = idx & 7;
            float4 v = make_float4(0.f, 0.f, 0.f, 0.f);
            if (row0 + r < n) v = *(const float4*)(x + (row0 + r) * 128 + kk + q * 4);
            sx4[r][q] = cvt4(v);
            float4 wv = *(const float4*)(W + r * 128 + kk + q * 4);
            sw4[r][q] = cvt4(wv);
        }
        __syncthreads();
#pragma unroll
        for (int k0 = 0; k0 < 32; k0 += 8) {
            unsigned int a[2][4], b[8][2];
#pragma unroll
            for (int mt = 0; mt < 2; mt++) {
                int rb = warp_m * 32 + mt * 16;
                a[mt][0] = sx[rb + g][k0 + tig];
                a[mt][1] = sx[rb + g + 8][k0 + tig];
                a[mt][2] = sx[rb + g][k0 + tig + 4];
                a[mt][3] = sx[rb + g + 8][k0 + tig + 4];
            }
#pragma unroll
            for (int nt = 0; nt < 8; nt++) {
                int cb = warp_n * 64 + nt * 8;
                b[nt][0] = sw[cb + g][k0 + tig];
                b[nt][1] = sw[cb + g][k0 + tig + 4];
            }
#pragma unroll
            for (int mt = 0; mt < 2; mt++)
#pragma unroll
                for (int nt = 0; nt < 8; nt++) mma8(acc[mt][nt], a[mt], b[nt]);
        }
    }

    // epilogue: bias add + store; for env path also s_dst/s_src scalars
#pragma unroll
    for (int mt = 0; mt < 2; mt++)
#pragma unroll
        for (int rr = 0; rr < 2; rr++) {
            int row = row0 + warp_m * 32 + mt * 16 + rr * 8 + g;
            float p1 = 0.f, p2 = 0.f;
            if (row < n) {
#pragma unroll
                for (int nt = 0; nt < 8; nt++) {
                    int col = warp_n * 64 + nt * 8 + tig * 2;
                    float v0 = acc[mt][nt][rr * 2 + 0] + bias[col];
                    float v1 = acc[mt][nt][rr * 2 + 1] + bias[col + 1];
                    *(float2*)(out + row * 128 + col) = make_float2(v0, v1);
                    if (env) {
                        p1 += v0 * envAw[col] + v1 * envAw[col + 1];
                        p2 += v0 * envAw[128 + col] + v1 * envAw[128 + col + 1];
                    }
                }
            }
            if (env) {
                p1 += __shfl_xor_sync(0xffffffffu, p1, 1);
                p1 += __shfl_xor_sync(0xffffffffu, p1, 2);
                p2 += __shfl_xor_sync(0xffffffffu, p2, 1);
                p2 += __shfl_xor_sync(0xffffffffu, p2, 2);
                if (tig == 0 && row < n) {
                    atomicAdd(&g_sdst_env[row], p1);
                    atomicAdd(&g_ssrc_env[row], p2);
                }
            }
        }
}

// ---------------- skinny in/out nets (8 outputs from x), weights in smem ----------------
__global__ __launch_bounds__(256) void k_skinny(const float* __restrict__ x,
    const float* __restrict__ inW, const float* __restrict__ inWb,
    const float* __restrict__ inAw,
    const float* __restrict__ inWres, const float* __restrict__ inWresb,
    const float* __restrict__ outW, const float* __restrict__ outWb,
    const float* __restrict__ outAw,
    const float* __restrict__ outWres, const float* __restrict__ outWresb,
    int n, int warps_total) {
    __shared__ float sW[8][128];
    int tid = threadIdx.x;
    for (int idx = tid; idx < 1024; idx += 256) {
        int j = idx >> 7, k = idx & 127;
        const float* p;
        switch (j) {
            case 0: p = inW; break;
            case 1: p = inW + 128; break;
            case 2: p = inWres; break;
            case 3: p = inWres + 128; break;
            case 4: p = outW; break;
            case 5: p = outW + 128; break;
            case 6: p = outWres; break;
            default: p = outWres + 128; break;
        }
        sW[j][k] = p[k];
    }
    __syncthreads();
    int lane = tid & 31;
    int warpg = blockIdx.x * 8 + (tid >> 5);
    for (int node = warpg; node < n; node += warps_total) {
        float4 xv = *(const float4*)(x + node * 128 + lane * 4);
        float f[8];
#pragma unroll
        for (int j = 0; j < 8; j++) {
            float4 w = *(const float4*)(&sW[j][lane * 4]);
            f[j] = xv.x * w.x + xv.y * w.y + xv.z * w.z + xv.w * w.w;
        }
#pragma unroll
        for (int off = 16; off > 0; off >>= 1)
#pragma unroll
            for (int j = 0; j < 8; j++) f[j] += __shfl_xor_sync(0xffffffffu, f[j], off);
        if (lane == 0) {
            float hinx = f[0] + inWb[0], hiny = f[1] + inWb[1];
            float houx = f[4] + outWb[0], houy = f[5] + outWb[1];
            g_hio[node] = make_float4(hinx, hiny, houx, houy);
            g_iolog[node] = make_float4(f[2] + inWresb[0], f[3] + inWresb[1],
                                        f[6] + outWresb[0], f[7] + outWresb[1]);
            g_sd_io[node] = make_float2(hinx * inAw[0] + hiny * inAw[1],
                                        houx * outAw[0] + houy * outAw[1]);
            g_ss_io[node] = make_float2(hinx * inAw[2] + hiny * inAw[3],
                                        houx * outAw[2] + houy * outAw[3]);
        }
    }
}

// ---------------- in/out segment softmax (exact, 3 passes) ----------------
__global__ void k_io1(const int* __restrict__ ei, const int* __restrict__ et, int E) {
    int e = blockIdx.x * blockDim.x + threadIdx.x;
    if (e >= E) return;
    int s = ei[e], d = ei[E + e], t = et[e];
    float2 sd = g_sd_io[d], ss = g_ss_io[s];
    float lin = lrelu(sd.x + ss.x + g_srel[t]);
    float lout = lrelu(sd.y + ss.y + g_srel[2 + t]);
    g_elog_io[e] = make_float2(lin, lout);
    atomicMax(&g_m_io[d].x, ford(lin));
    atomicMax(&g_m_io[d].y, ford(lout));
}

__global__ void k_io2(const int* __restrict__ ei, int E) {
    int e = blockIdx.x * blockDim.x + threadIdx.x;
    if (e >= E) return;
    int d = ei[E + e];
    int2 m = g_m_io[d];
    float2 l = g_elog_io[e];
    float ein = expf(l.x - funord(m.x));
    float eout = expf(l.y - funord(m.y));
    g_e_io[e] = make_float2(ein, eout);
    red_add_v2(&g_den_io[d], ein, eout);
}

__global__ void k_rden(int n) {
    int i = blockIdx.x * blockDim.x + threadIdx.x;
    if (i >= n) return;
    float2 dd = g_den_io[i];
    g_rden_io[i] = make_float2(1.f / fmaxf(dd.x, 1e-16f), 1.f / fmaxf(dd.y, 1e-16f));
}

__global__ void k_io3(const int* __restrict__ ei, int E) {
    int e = blockIdx.x * blockDim.x + threadIdx.x;
    if (e >= E) return;
    int s = ei[e], d = ei[E + e];
    float2 ev = g_e_io[e];
    float2 rd = g_rden_io[d];
    float ain = ev.x * rd.x, aout = ev.y * rd.y;
    float4 h = g_hio[s];
    red_add_v4((float*)&g_iolog[d], ain * h.x, ain * h.y, aout * h.z, aout * h.w);
}

__global__ void k_decide(const float* __restrict__ gi, const float* __restrict__ go, int n) {
    int i = blockIdx.x * blockDim.x + threadIdx.x;
    if (i >= n) return;
    float4 il = g_iolog[i];
    float2 a = ((const float2*)gi)[i];
    float2 b = ((const float2*)go)[i];
    unsigned char kin = (il.x + a.x) >= (il.y + a.y) ? 1 : 0;
    unsigned char kout = (il.z + b.x) >= (il.w + b.y) ? 2 : 0;
    g_keep[i] = kin | kout;
}

// ---------------- env softmax (no max pass needed: bounded logits) ----------------
__global__ void k_env1(const int* __restrict__ ei, const int* __restrict__ et, int E) {
    int e = blockIdx.x * blockDim.x + threadIdx.x;
    if (e >= E) return;
    int s = ei[e], d = ei[E + e];
    float ev = 0.f;
    if ((g_keep[d] & 1) && (g_keep[s] & 2)) {
        int t = et[e];
        float l = lrelu(g_sdst_env[d] + g_ssrc_env[s] + g_srel[4 + t]);
        ev = __expf(l);
        atomicAdd(&g_den_env[d], ev);
    }
    g_e_env[e] = ev;
}

// heavy aggregation: one warp per edge, float4 vector reductions into d_out
__global__ void k_env3(const int* __restrict__ ei, float* __restrict__ out, int E) {
    int w = (blockIdx.x * blockDim.x + threadIdx.x) >> 5;
    int lane = threadIdx.x & 31;
    if (w >= E) return;
    float ev = g_e_env[w];
    if (ev == 0.f) return;
    int d = ei[E + w];
    float alpha = __fdividef(ev, g_den_env[d]);
    int s = ei[w];
    float4 hv = ((const float4*)g_h_env)[s * 32 + lane];
    red_add_v4(out + d * 128 + lane * 4, alpha * hv.x, alpha * hv.y, alpha * hv.z, alpha * hv.w);
}

// ---------------- launch ----------------
extern "C" void kernel_launch(void* const* d_in, const int* in_sizes, int n_in,
                              void* d_out, int out_size) {
    const float* x = (const float*)d_in[0];
    const int* ei = (const int*)d_in[1];
    const int* et = (const int*)d_in[2];
    const float* gi = (const float*)d_in[3];
    const float* go = (const float*)d_in[4];
    const float* inW = (const float*)d_in[5];
    const float* inWb = (const float*)d_in[6];
    const float* inWr = (const float*)d_in[7];
    const float* inWrb = (const float*)d_in[8];
    const float* inAw = (const float*)d_in[9];
    const float* inAb = (const float*)d_in[10];
    const float* inWres = (const float*)d_in[11];
    const float* inWresb = (const float*)d_in[12];
    const float* inRel = (const float*)d_in[13];
    const float* outW = (const float*)d_in[14];
    const float* outWb = (const float*)d_in[15];
    const float* outWr = (const float*)d_in[16];
    const float* outWrb = (const float*)d_in[17];
    const float* outAw = (const float*)d_in[18];
    const float* outAb = (const float*)d_in[19];
    const float* outWres = (const float*)d_in[20];
    const float* outWresb = (const float*)d_in[21];
    const float* outRel = (const float*)d_in[22];
    const float* envW = (const float*)d_in[23];
    const float* envWb = (const float*)d_in[24];
    const float* envWr = (const float*)d_in[25];
    const float* envWrb = (const float*)d_in[26];
    const float* envAw = (const float*)d_in[27];
    const float* envAb = (const float*)d_in[28];
    const float* envWres = (const float*)d_in[29];
    const float* envWresb = (const float*)d_in[30];
    const float* envRel = (const float*)d_in[31];

    float* out = (float*)d_out;
    int n = in_sizes[0] / 128;
    int E = in_sizes[2];
    int nb = (n + 255) / 256;

    k_initrel<<<nb + 1, 256>>>(inWr, inWrb, inAw, inAb, inRel,
                               outWr, outWrb, outAw, outAb, outRel,
                               envWr, envWrb, envAw, envAb, envRel, n);
    k_gemm<<<dim3((n + 127) / 128, 2), 256>>>(x, envW, envWb, envWres, envWresb,
                                              envAw, out, n);
    k_skinny<<<1184, 256>>>(x, inW, inWb, inAw, inWres, inWresb,
                            outW, outWb, outAw, outWres, outWresb, n, 1184 * 8);
    k_io1<<<(E + 255) / 256, 256>>>(ei, et, E);
    k_io2<<<(E + 255) / 256, 256>>>(ei, E);
    k_rden<<<nb, 256>>>(n);
    k_io3<<<(E + 255) / 256, 256>>>(ei, E);
    k_decide<<<nb, 256>>>(gi, go, n);
    k_env1<<<(E + 255) / 256, 256>>>(ei, et, E);
    k_env3<<<(E * 32 + 255) / 256, 256>>>(ei, out, E);
}

// round 7
// speedup vs baseline: 2.1038x; 1.3256x over previous
#include <cuda_runtime.h>
#include <math.h>

#define MAXN 50048
#define MAXE 640000

// ---------------- scratch (device globals) ----------------
__device__ float g_h_env[MAXN * 128];
__device__ float g_sdst_env[MAXN];     // after k_decide: masked with -1e30
__device__ float g_ssrc_env[MAXN];     // after k_decide: masked with -1e30
__device__ float2 g_sd_io[MAXN];       // (sdst_in, sdst_out)
__device__ float2 g_ss_io[MAXN];       // (ssrc_in, ssrc_out)
__device__ float4 g_hio[MAXN];         // (h_in.x, h_in.y, h_out.x, h_out.y)
__device__ float4 g_iolog[MAXN];       // (in0, in1, out0, out1) residual + aggr
__device__ float2 g_den_io[MAXN];
__device__ float  g_den_env[MAXN];
__device__ float2 g_e_io[MAXE];
__device__ float g_srel[8];            // [0,1]=in(+bias)  [2,3]=out(+bias)  [4,5]=env(+bias)
// compacted surviving env edges
__device__ int  g_cnt;
__device__ int2 g_ce[MAXE];
__device__ float g_cev[MAXE];

// ---------------- helpers ----------------
__device__ __forceinline__ float lrelu(float v) { return v >= 0.f ? v : 0.2f * v; }

__device__ __forceinline__ void red_add_v2(float2* p, float a, float b) {
    asm volatile("red.global.add.v2.f32 [%0], {%1, %2};"
                 :: "l"(p), "f"(a), "f"(b) : "memory");
}
__device__ __forceinline__ void red_add_v4(float* p, float a, float b, float c, float d) {
    asm volatile("red.global.add.v4.f32 [%0], {%1, %2, %3, %4};"
                 :: "l"(p), "f"(a), "f"(b), "f"(c), "f"(d) : "memory");
}
__device__ __forceinline__ unsigned int cvt_tf32(float v) {
    unsigned int r;
    asm("cvt.rna.tf32.f32 %0, %1;" : "=r"(r) : "f"(v));
    return r;
}
__device__ __forceinline__ uint4 cvt4(float4 v) {
    return make_uint4(cvt_tf32(v.x), cvt_tf32(v.y), cvt_tf32(v.z), cvt_tf32(v.w));
}
__device__ __forceinline__ void mma8(float* c, const unsigned int* a, const unsigned int* b) {
    asm volatile(
        "mma.sync.aligned.m16n8k8.row.col.f32.tf32.tf32.f32 "
        "{%0,%1,%2,%3}, {%4,%5,%6,%7}, {%8,%9}, {%0,%1,%2,%3};"
        : "+f"(c[0]), "+f"(c[1]), "+f"(c[2]), "+f"(c[3])
        : "r"(a[0]), "r"(a[1]), "r"(a[2]), "r"(a[3]), "r"(b[0]), "r"(b[1]));
}

// ---------------- init + s_rel (block 0 = rel, rest = init) ----------------
__global__ void k_initrel(const float* __restrict__ inWr, const float* __restrict__ inWrb,
                          const float* __restrict__ inAw, const float* __restrict__ inAb,
                          const float* __restrict__ inRel,
                          const float* __restrict__ outWr, const float* __restrict__ outWrb,
                          const float* __restrict__ outAw, const float* __restrict__ outAb,
                          const float* __restrict__ outRel,
                          const float* __restrict__ envWr, const float* __restrict__ envWrb,
                          const float* __restrict__ envAw, const float* __restrict__ envAb,
                          const float* __restrict__ envRel, int n) {
    int t = threadIdx.x;
    if (blockIdx.x == 0) {
        __shared__ float red[128];
        for (int tt = 0; tt < 2; tt++) {
            if (t < 128) {
                float r = envWrb[t];
                for (int k = 0; k < 100; k++) r += envRel[tt * 100 + k] * envWr[t * 100 + k];
                red[t] = r * envAw[256 + t];
            }
            __syncthreads();
            for (int s2 = 64; s2 > 0; s2 >>= 1) {
                if (t < s2) red[t] += red[t + s2];
                __syncthreads();
            }
            if (t == 0) g_srel[4 + tt] = red[0] + envAb[0];
            __syncthreads();
        }
        if (t == 0) {
            g_cnt = 0;
            for (int tt = 0; tt < 2; tt++) {
                float s = 0.f;
                for (int j = 0; j < 2; j++) {
                    float r = inWrb[j];
                    for (int k = 0; k < 100; k++) r += inRel[tt * 100 + k] * inWr[j * 100 + k];
                    s += r * inAw[4 + j];
                }
                g_srel[tt] = s + inAb[0];
            }
        } else if (t == 32) {
            for (int tt = 0; tt < 2; tt++) {
                float s = 0.f;
                for (int j = 0; j < 2; j++) {
                    float r = outWrb[j];
                    for (int k = 0; k < 100; k++) r += outRel[tt * 100 + k] * outWr[j * 100 + k];
                    s += r * outAw[4 + j];
                }
                g_srel[2 + tt] = s + outAb[0];
            }
        }
    } else {
        int i = (blockIdx.x - 1) * 256 + t;
        if (i < n) {
            g_den_io[i] = make_float2(0.f, 0.f);
            g_den_env[i] = 0.f;
            g_sdst_env[i] = 0.f;
            g_ssrc_env[i] = 0.f;
        }
    }
}

// ---------------- tf32 tensor-core GEMM: y = x @ W^T + b ----------------
// blockIdx.y==0 -> envW into g_h_env (+ env attention scalar epilogue)
// blockIdx.y==1 -> envWres into d_out (residual)
__global__ __launch_bounds__(256) void k_gemm(const float* __restrict__ x,
                                              const float* __restrict__ W0,
                                              const float* __restrict__ b0,
                                              const float* __restrict__ W1,
                                              const float* __restrict__ b1,
                                              const float* __restrict__ envAw,
                                              float* __restrict__ out1, int n) {
    const float* W = blockIdx.y ? W1 : W0;
    const float* bias = blockIdx.y ? b1 : b0;
    float* out = blockIdx.y ? out1 : g_h_env;
    const bool env = (blockIdx.y == 0);

    __shared__ uint4 sx4[128][9];   // 128 rows x 32 k, stride 36 floats (pad 4)
    __shared__ uint4 sw4[128][9];
    unsigned int (*sx)[36] = reinterpret_cast<unsigned int(*)[36]>(sx4);
    unsigned int (*sw)[36] = reinterpret_cast<unsigned int(*)[36]>(sw4);

    int tid = threadIdx.x;
    int lane = tid & 31;
    int wid = tid >> 5;
    int warp_m = wid >> 1;      // 0..3 -> 32-row tile
    int warp_n = wid & 1;       // 0..1 -> 64-col tile
    int g = lane >> 2, tig = lane & 3;
    int row0 = blockIdx.x * 128;

    float acc[2][8][4];
#pragma unroll
    for (int mt = 0; mt < 2; mt++)
#pragma unroll
        for (int nt = 0; nt < 8; nt++)
#pragma unroll
            for (int q = 0; q < 4; q++) acc[mt][nt][q] = 0.f;

    for (int kk = 0; kk < 128; kk += 32) {
        __syncthreads();
#pragma unroll
        for (int idx = tid; idx < 1024; idx += 256) {
            int r = idx >> 3, q = idx & 7;
            float4 v = make_float4(0.f, 0.f, 0.f, 0.f);
            if (row0 + r < n) v = *(const float4*)(x + (row0 + r) * 128 + kk + q * 4);
            sx4[r][q] = cvt4(v);
            float4 wv = *(const float4*)(W + r * 128 + kk + q * 4);
            sw4[r][q] = cvt4(wv);
        }
        __syncthreads();
#pragma unroll
        for (int k0 = 0; k0 < 32; k0 += 8) {
            unsigned int a[2][4], b[8][2];
#pragma unroll
            for (int mt = 0; mt < 2; mt++) {
                int rb = warp_m * 32 + mt * 16;
                a[mt][0] = sx[rb + g][k0 + tig];
                a[mt][1] = sx[rb + g + 8][k0 + tig];
                a[mt][2] = sx[rb + g][k0 + tig + 4];
                a[mt][3] = sx[rb + g + 8][k0 + tig + 4];
            }
#pragma unroll
            for (int nt = 0; nt < 8; nt++) {
                int cb = warp_n * 64 + nt * 8;
                b[nt][0] = sw[cb + g][k0 + tig];
                b[nt][1] = sw[cb + g][k0 + tig + 4];
            }
#pragma unroll
            for (int mt = 0; mt < 2; mt++)
#pragma unroll
                for (int nt = 0; nt < 8; nt++) mma8(acc[mt][nt], a[mt], b[nt]);
        }
    }

    // epilogue: bias add + store; for env path also s_dst/s_src scalars
#pragma unroll
    for (int mt = 0; mt < 2; mt++)
#pragma unroll
        for (int rr = 0; rr < 2; rr++) {
            int row = row0 + warp_m * 32 + mt * 16 + rr * 8 + g;
            float p1 = 0.f, p2 = 0.f;
            if (row < n) {
#pragma unroll
                for (int nt = 0; nt < 8; nt++) {
                    int col = warp_n * 64 + nt * 8 + tig * 2;
                    float v0 = acc[mt][nt][rr * 2 + 0] + bias[col];
                    float v1 = acc[mt][nt][rr * 2 + 1] + bias[col + 1];
                    *(float2*)(out + row * 128 + col) = make_float2(v0, v1);
                    if (env) {
                        p1 += v0 * envAw[col] + v1 * envAw[col + 1];
                        p2 += v0 * envAw[128 + col] + v1 * envAw[128 + col + 1];
                    }
                }
            }
            if (env) {
                p1 += __shfl_xor_sync(0xffffffffu, p1, 1);
                p1 += __shfl_xor_sync(0xffffffffu, p1, 2);
                p2 += __shfl_xor_sync(0xffffffffu, p2, 1);
                p2 += __shfl_xor_sync(0xffffffffu, p2, 2);
                if (tig == 0 && row < n) {
                    atomicAdd(&g_sdst_env[row], p1);
                    atomicAdd(&g_ssrc_env[row], p2);
                }
            }
        }
}

// ---------------- skinny in/out nets (8 outputs from x), weights in smem ----------------
__global__ __launch_bounds__(256) void k_skinny(const float* __restrict__ x,
    const float* __restrict__ inW, const float* __restrict__ inWb,
    const float* __restrict__ inAw,
    const float* __restrict__ inWres, const float* __restrict__ inWresb,
    const float* __restrict__ outW, const float* __restrict__ outWb,
    const float* __restrict__ outAw,
    const float* __restrict__ outWres, const float* __restrict__ outWresb,
    int n, int warps_total) {
    __shared__ float sW[8][128];
    int tid = threadIdx.x;
    for (int idx = tid; idx < 1024; idx += 256) {
        int j = idx >> 7, k = idx & 127;
        const float* p;
        switch (j) {
            case 0: p = inW; break;
            case 1: p = inW + 128; break;
            case 2: p = inWres; break;
            case 3: p = inWres + 128; break;
            case 4: p = outW; break;
            case 5: p = outW + 128; break;
            case 6: p = outWres; break;
            default: p = outWres + 128; break;
        }
        sW[j][k] = p[k];
    }
    __syncthreads();
    int lane = tid & 31;
    int warpg = blockIdx.x * 8 + (tid >> 5);
    for (int node = warpg; node < n; node += warps_total) {
        float4 xv = *(const float4*)(x + node * 128 + lane * 4);
        float f[8];
#pragma unroll
        for (int j = 0; j < 8; j++) {
            float4 w = *(const float4*)(&sW[j][lane * 4]);
            f[j] = xv.x * w.x + xv.y * w.y + xv.z * w.z + xv.w * w.w;
        }
#pragma unroll
        for (int off = 16; off > 0; off >>= 1)
#pragma unroll
            for (int j = 0; j < 8; j++) f[j] += __shfl_xor_sync(0xffffffffu, f[j], off);
        if (lane == 0) {
            float hinx = f[0] + inWb[0], hiny = f[1] + inWb[1];
            float houx = f[4] + outWb[0], houy = f[5] + outWb[1];
            g_hio[node] = make_float4(hinx, hiny, houx, houy);
            g_iolog[node] = make_float4(f[2] + inWresb[0], f[3] + inWresb[1],
                                        f[6] + outWresb[0], f[7] + outWresb[1]);
            g_sd_io[node] = make_float2(hinx * inAw[0] + hiny * inAw[1],
                                        houx * outAw[0] + houy * outAw[1]);
            g_ss_io[node] = make_float2(hinx * inAw[2] + hiny * inAw[3],
                                        houx * outAw[2] + houy * outAw[3]);
        }
    }
}

// ---------------- in/out softmax pass A: logits + exp + denom (no max pass) ----------------
__global__ void k_ioA(const int* __restrict__ ei, const int* __restrict__ et, int E) {
    int t = blockIdx.x * blockDim.x + threadIdx.x;
    int T = E >> 2;
    if (t >= T) return;
    float4 sr = *(const float4*)g_srel;   // in t0, in t1, out t0, out t1
#pragma unroll
    for (int q = 0; q < 4; q++) {
        int e = t + q * T;
        int s = ei[e], d = ei[E + e], ty = et[e];
        float2 sd = g_sd_io[d], ss = g_ss_io[s];
        float lin = lrelu(sd.x + ss.x + (ty ? sr.y : sr.x));
        float lou = lrelu(sd.y + ss.y + (ty ? sr.w : sr.z));
        float ein = expf(lin);
        float eout = expf(lou);
        g_e_io[e] = make_float2(ein, eout);
        red_add_v2(&g_den_io[d], ein, eout);
    }
}

// ---------------- in/out softmax pass B: alpha * h aggregation ----------------
__global__ void k_io3(const int* __restrict__ ei, int E) {
    int t = blockIdx.x * blockDim.x + threadIdx.x;
    int T = E >> 2;
    if (t >= T) return;
#pragma unroll
    for (int q = 0; q < 4; q++) {
        int e = t + q * T;
        int s = ei[e], d = ei[E + e];
        float2 ev = g_e_io[e];
        float2 den = g_den_io[d];
        float ain = ev.x / fmaxf(den.x, 1e-16f);
        float aout = ev.y / fmaxf(den.y, 1e-16f);
        float4 h = g_hio[s];
        red_add_v4((float*)&g_iolog[d], ain * h.x, ain * h.y, aout * h.z, aout * h.w);
    }
}

// ---------------- decide: argmax of (aggr+res+gumbel), mask env scalars in-place ----------------
__global__ void k_decide(const float* __restrict__ gi, const float* __restrict__ go, int n) {
    int i = blockIdx.x * blockDim.x + threadIdx.x;
    if (i >= n) return;
    float4 il = g_iolog[i];
    float2 a = ((const float2*)gi)[i];
    float2 b = ((const float2*)go)[i];
    bool kin = (il.x + a.x) >= (il.y + a.y);
    bool kout = (il.z + b.x) >= (il.w + b.y);
    if (!kin) g_sdst_env[i] = -1e30f;
    if (!kout) g_ssrc_env[i] = -1e30f;
}

// ---------------- env pass 1: masked logits, exp, denom, compaction ----------------
__global__ __launch_bounds__(256) void k_env1(const int* __restrict__ ei,
                                              const int* __restrict__ et, int E) {
    __shared__ int sCnt, sBase;
    if (threadIdx.x == 0) sCnt = 0;
    __syncthreads();
    int t = blockIdx.x * blockDim.x + threadIdx.x;
    int T = E >> 2;
    float sr4 = g_srel[4], sr5 = g_srel[5];
    int cnt = 0;
    int2 se[4];
    float evv[4];
    if (t < T) {
#pragma unroll
        for (int q = 0; q < 4; q++) {
            int e = t + q * T;
            int s = ei[e], d = ei[E + e];
            float l = g_sdst_env[d] + g_ssrc_env[s];
            if (l > -1e20f) {
                l = lrelu(l + (et[e] ? sr5 : sr4));
                float ev = __expf(l);
                atomicAdd(&g_den_env[d], ev);
                se[cnt] = make_int2(s, d);
                evv[cnt] = ev;
                cnt++;
            }
        }
    }
    int off = atomicAdd(&sCnt, cnt);
    __syncthreads();
    if (threadIdx.x == 0) sBase = atomicAdd(&g_cnt, sCnt);
    __syncthreads();
    int base = sBase + off;
    for (int i = 0; i < cnt; i++) {
        g_ce[base + i] = se[i];
        g_cev[base + i] = evv[i];
    }
}

// ---------------- env pass 2: persistent warps over compacted edges ----------------
__global__ void k_env3(float* __restrict__ out) {
    int nW = (gridDim.x * blockDim.x) >> 5;
    int w = (blockIdx.x * blockDim.x + threadIdx.x) >> 5;
    int lane = threadIdx.x & 31;
    int cnt = g_cnt;
    for (; w < cnt; w += nW) {
        int2 sd = g_ce[w];
        float alpha = __fdividef(g_cev[w], g_den_env[sd.y]);
        float4 hv = ((const float4*)g_h_env)[sd.x * 32 + lane];
        red_add_v4(out + sd.y * 128 + lane * 4,
                   alpha * hv.x, alpha * hv.y, alpha * hv.z, alpha * hv.w);
    }
}

// ---------------- launch ----------------
extern "C" void kernel_launch(void* const* d_in, const int* in_sizes, int n_in,
                              void* d_out, int out_size) {
    const float* x = (const float*)d_in[0];
    const int* ei = (const int*)d_in[1];
    const int* et = (const int*)d_in[2];
    const float* gi = (const float*)d_in[3];
    const float* go = (const float*)d_in[4];
    const float* inW = (const float*)d_in[5];
    const float* inWb = (const float*)d_in[6];
    const float* inWr = (const float*)d_in[7];
    const float* inWrb = (const float*)d_in[8];
    const float* inAw = (const float*)d_in[9];
    const float* inAb = (const float*)d_in[10];
    const float* inWres = (const float*)d_in[11];
    const float* inWresb = (const float*)d_in[12];
    const float* inRel = (const float*)d_in[13];
    const float* outW = (const float*)d_in[14];
    const float* outWb = (const float*)d_in[15];
    const float* outWr = (const float*)d_in[16];
    const float* outWrb = (const float*)d_in[17];
    const float* outAw = (const float*)d_in[18];
    const float* outAb = (const float*)d_in[19];
    const float* outWres = (const float*)d_in[20];
    const float* outWresb = (const float*)d_in[21];
    const float* outRel = (const float*)d_in[22];
    const float* envW = (const float*)d_in[23];
    const float* envWb = (const float*)d_in[24];
    const float* envWr = (const float*)d_in[25];
    const float* envWrb = (const float*)d_in[26];
    const float* envAw = (const float*)d_in[27];
    const float* envAb = (const float*)d_in[28];
    const float* envWres = (const float*)d_in[29];
    const float* envWresb = (const float*)d_in[30];
    const float* envRel = (const float*)d_in[31];

    float* out = (float*)d_out;
    int n = in_sizes[0] / 128;
    int E = in_sizes[2];
    int nb = (n + 255) / 256;
    int T = E >> 2;                 // 4 edges per thread
    int eb = (T + 255) / 256;

    k_initrel<<<nb + 1, 256>>>(inWr, inWrb, inAw, inAb, inRel,
                               outWr, outWrb, outAw, outAb, outRel,
                               envWr, envWrb, envAw, envAb, envRel, n);
    k_gemm<<<dim3((n + 127) / 128, 2), 256>>>(x, envW, envWb, envWres, envWresb,
                                              envAw, out, n);
    k_skinny<<<1184, 256>>>(x, inW, inWb, inAw, inWres, inWresb,
                            outW, outWb, outAw, outWres, outWresb, n, 1184 * 8);
    k_ioA<<<eb, 256>>>(ei, et, E);
    k_io3<<<eb, 256>>>(ei, E);
    k_decide<<<nb, 256>>>(gi, go, n);
    k_env1<<<eb, 256>>>(ei, et, E);
    k_env3<<<1184, 256>>>(out);
}